// round 2
// baseline (speedup 1.0000x reference)
#include <cuda_runtime.h>

// QNNClassifier: 14-qubit statevector sim, BATCH=2048, DEPTH=8.
// Strategy: one CTA per batch element; full state (16384 complex64 as SoA
// float re/im) lives in shared memory. CX gates are deferred as a GF(2)-linear
// relabeling (mask pairs f_q = row q of sigma^-1, v_q = column q of sigma), so
// only the 112 fused RZ+RY butterflies touch the state. Initial RY layer on
// |0> is materialized directly as a product state via two 128-entry tables.

#define NQ       14
#define QDIM     16384          // 2^14
#define DEPTH    8
#define NGATES   (DEPTH * NQ)   // 112
#define NTHREADS 1024

__global__ __launch_bounds__(NTHREADS, 1)
void qnn_kernel(const float* __restrict__ x,
                const float* __restrict__ params,
                float* __restrict__ out)
{
    extern __shared__ float smem[];
    float* sRe = smem;          // [QDIM]
    float* sIm = smem + QDIM;   // [QDIM]

    __shared__ float gU[NGATES][8];   // fused RZ*RY 2x2 complex constants
    __shared__ int   gF[NGATES];      // parity mask (row of sigma^-1)
    __shared__ int   gV[NGATES];      // flip mask   (col of sigma)
    __shared__ int   sFfin;           // final measurement parity mask
    __shared__ float cq[NQ], sq[NQ];  // initial RY cos/sin per qubit
    __shared__ float tabLo[128], tabHi[128];
    __shared__ float redbuf[NTHREADS / 32];

    const int tid = threadIdx.x;
    const int b   = blockIdx.x;

    // ---- per-qubit init-RY cos/sin: angle = x * pi / 2 ----
    if (tid < NQ) {
        float ang = x[b * NQ + tid] * 1.57079632679489662f;
        float s, c;
        sincosf(ang, &s, &c);
        cq[tid] = c;
        sq[tid] = s;
    }

    // ---- mask evolution through the CX ring (thread 14, sequential, cheap) ----
    if (tid == NQ) {
        int v[NQ], f[NQ];
        #pragma unroll
        for (int q = 0; q < NQ; ++q) { v[q] = 1 << (NQ - 1 - q); f[q] = v[q]; }
        for (int l = 0; l < DEPTH; ++l) {
            for (int q = 0; q < NQ; ++q) { gF[l * NQ + q] = f[q]; gV[l * NQ + q] = v[q]; }
            // CX ring applied AFTER the layer's single-qubit gates:
            // state' = state[perm]  =>  sigma <- sigma * P:
            //   v_c ^= v_t (column update), f_t ^= f_c (row update)
            for (int c = 0; c < NQ; ++c) {
                int t = (c + 1) % NQ;
                v[c] ^= v[t];
                f[t] ^= f[c];
            }
        }
        sFfin = f[0];   // measurement = Z on qubit 0 (idx < DIM/2 sign)
    }

    // ---- fused RZ+RY constants, one gate per thread (threads 32..143) ----
    if (tid >= 32 && tid < 32 + NGATES) {
        int g = tid - 32;
        float tz = params[2 * g];
        float ty = params[2 * g + 1];
        float sy, cy; sincosf(0.5f * ty, &sy, &cy);
        float sz, cz; sincosf(0.5f * tz, &sz, &cz);
        // p0 = e^{-i tz/2} (bit=0), p1 = e^{+i tz/2} (bit=1); RY = [[c,-s],[s,c]]
        // U = RY * diag(p0, p1)
        gU[g][0] =  cy * cz;  gU[g][1] = -cy * sz;   // u00 = c*p0
        gU[g][2] = -sy * cz;  gU[g][3] = -sy * sz;   // u01 = -s*p1
        gU[g][4] =  sy * cz;  gU[g][5] = -sy * sz;   // u10 = s*p0
        gU[g][6] =  cy * cz;  gU[g][7] =  cy * sz;   // u11 = c*p1
    }
    __syncthreads();

    // ---- product-state tables ----
    // bit position k (from LSB) corresponds to qubit (13 - k)
    if (tid < 128) {
        float p = 1.0f;
        #pragma unroll
        for (int k = 0; k < 7; ++k)
            p *= ((tid >> k) & 1) ? sq[NQ - 1 - k] : cq[NQ - 1 - k];
        tabLo[tid] = p;
    } else if (tid < 256) {
        int m = tid - 128;
        float p = 1.0f;
        #pragma unroll
        for (int k = 0; k < 7; ++k)
            p *= ((m >> k) & 1) ? sq[6 - k] : cq[6 - k];  // positions 7..13 -> qubits 6..0
        tabHi[m] = p;
    }
    __syncthreads();

    // ---- initialize state (exact product state after the encoding RY layer) ----
    #pragma unroll
    for (int k = 0; k < QDIM / NTHREADS; ++k) {
        int j = tid + k * NTHREADS;
        sRe[j] = tabHi[j >> 7] * tabLo[j & 127];
        sIm[j] = 0.0f;
    }

    // ---- 112 fused RZ+RY butterflies on generalized qubits ----
    for (int g = 0; g < NGATES; ++g) {
        __syncthreads();
        const int f = gF[g];
        const int v = gV[g];
        const float u00r = gU[g][0], u00i = gU[g][1];
        const float u01r = gU[g][2], u01i = gU[g][3];
        const float u10r = gU[g][4], u10i = gU[g][5];
        const float u11r = gU[g][6], u11i = gU[g][7];
        const int bp = __ffs(v) - 1;      // pivot bit of flip mask (f&v parity = 1)
        const int lm = (1 << bp) - 1;

        #pragma unroll
        for (int k = 0; k < (QDIM / 2) / NTHREADS; ++k) {
            int p  = tid + k * NTHREADS;
            int j0 = ((p & ~lm) << 1) | (p & lm);   // insert 0 at pivot bit
            int j1 = j0 ^ v;

            float xr0 = sRe[j0], xi0 = sIm[j0];
            float xr1 = sRe[j1], xi1 = sIm[j1];
            bool sw = (__popc(f & j0) & 1) != 0;    // j0 is the |1> element?

            float a0r = sw ? xr1 : xr0;
            float a0i = sw ? xi1 : xi0;
            float a1r = sw ? xr0 : xr1;
            float a1i = sw ? xi0 : xi1;

            float y0r = u00r * a0r - u00i * a0i + u01r * a1r - u01i * a1i;
            float y0i = u00r * a0i + u00i * a0r + u01r * a1i + u01i * a1r;
            float y1r = u10r * a0r - u10i * a0i + u11r * a1r - u11i * a1i;
            float y1i = u10r * a0i + u10i * a0r + u11r * a1i + u11i * a1r;

            sRe[j0] = sw ? y1r : y0r;
            sIm[j0] = sw ? y1i : y0i;
            sRe[j1] = sw ? y0r : y1r;
            sIm[j1] = sw ? y0i : y1i;
        }
    }
    __syncthreads();

    // ---- expectation value: sum |amp|^2 * (+1 if parity(fFinal & j)==0 else -1) ----
    const int ff = sFfin;
    float acc = 0.0f;
    #pragma unroll
    for (int k = 0; k < QDIM / NTHREADS; ++k) {
        int j = tid + k * NTHREADS;
        float pr = sRe[j] * sRe[j] + sIm[j] * sIm[j];
        acc += (__popc(ff & j) & 1) ? -pr : pr;
    }
    #pragma unroll
    for (int off = 16; off > 0; off >>= 1)
        acc += __shfl_down_sync(0xffffffffu, acc, off);
    if ((tid & 31) == 0) redbuf[tid >> 5] = acc;
    __syncthreads();
    if (tid < 32) {
        float t = redbuf[tid];
        #pragma unroll
        for (int off = 16; off > 0; off >>= 1)
            t += __shfl_down_sync(0xffffffffu, t, off);
        if (tid == 0) out[b] = (t + 1.0f) * 0.5f;
    }
}

extern "C" void kernel_launch(void* const* d_in, const int* in_sizes, int n_in,
                              void* d_out, int out_size)
{
    const float* x      = (const float*)d_in[0];   // (2048, 14) float32
    const float* params = (const float*)d_in[1];   // (224,)    float32
    float* out          = (float*)d_out;           // (2048,)   float32

    (void)in_sizes; (void)n_in;

    const size_t shmem = (size_t)2 * QDIM * sizeof(float);  // 128 KB state
    cudaFuncSetAttribute(qnn_kernel,
                         cudaFuncAttributeMaxDynamicSharedMemorySize,
                         (int)shmem);

    qnn_kernel<<<out_size, NTHREADS, shmem>>>(x, params, out);
}

// round 3
// speedup vs baseline: 1.9722x; 1.9722x over previous
#include <cuda_runtime.h>

// QNNClassifier: 14-qubit statevector, BATCH=2048, DEPTH=8.
// One CTA per batch element; state = 16384 float2 in shared memory (128 KB).
// CX gates are deferred as GF(2) index relabeling (masks f,v per gate).
// 112 fused RZ+RY gates are applied 4-at-a-time: the 4 flip masks are
// linearly independent, so the state splits into 1024 cosets of 16 amps;
// each thread register-caches a coset, applies 4 butterflies, stores once.
// Parity roles are handled by sign-bit XOR (no selects).

#define NQ       14
#define QDIM     16384
#define DEPTH    8
#define NGATES   (DEPTH * NQ)     // 112
#define NPASS    (NGATES / 4)     // 28
#define NTHREADS 512

struct Consts {
    int   piv[NPASS][4];          // sorted pivot bits (coset representative enumeration)
    int   V[NPASS][16];           // XOR offset per in-coset position t
    int   F[NPASS][4];            // parity masks per gate
    int   lut[NPASS][4];          // 16-bit LUT: parity(F & V[t]) per t
    float trig[NPASS][4][4];      // cz, sz, cy, sy per gate
    int   ffin;                   // final measurement parity mask
};
__device__ Consts dC;

// ---------------- setup kernel: masks, elimination, LUTs, trig ----------------
__global__ void qnn_setup(const float* __restrict__ params)
{
    __shared__ int vg[NGATES], fg[NGATES];
    const int tid = threadIdx.x;

    if (tid == 0) {
        int v[NQ], f[NQ];
        #pragma unroll
        for (int q = 0; q < NQ; ++q) { v[q] = 1 << (NQ - 1 - q); f[q] = v[q]; }
        for (int l = 0; l < DEPTH; ++l) {
            for (int q = 0; q < NQ; ++q) { fg[l * NQ + q] = f[q]; vg[l * NQ + q] = v[q]; }
            for (int c = 0; c < NQ; ++c) {           // CX ring after the layer
                int t = (c + 1) % NQ;
                v[c] ^= v[t];
                f[t] ^= f[c];
            }
        }
        dC.ffin = f[0];
    }
    __syncthreads();

    if (tid < NGATES) {
        float tz = params[2 * tid];
        float ty = params[2 * tid + 1];
        float sz, cz, sy, cy;
        sincosf(0.5f * tz, &sz, &cz);
        sincosf(0.5f * ty, &sy, &cy);
        int p = tid >> 2, i = tid & 3;
        dC.trig[p][i][0] = cz; dC.trig[p][i][1] = sz;
        dC.trig[p][i][2] = cy; dC.trig[p][i][3] = sy;
        dC.F[p][i] = fg[tid];
    }

    if (tid < NPASS) {
        int m[4];
        #pragma unroll
        for (int i = 0; i < 4; ++i) m[i] = vg[4 * tid + i];

        // Gaussian elimination (GF2) to find 4 distinct pivot bits
        int u[4], bp[4];
        #pragma unroll
        for (int i = 0; i < 4; ++i) {
            u[i] = m[i];
            for (int j = 0; j < i; ++j)
                if ((u[i] >> bp[j]) & 1) u[i] ^= u[j];
            bp[i] = 31 - __clz(u[i]);                 // highest set bit as pivot
            for (int j = 0; j < i; ++j)
                if ((u[j] >> bp[i]) & 1) u[j] ^= u[i];
        }
        // sort pivots ascending (4-element network)
        #pragma unroll
        for (int a = 0; a < 3; ++a)
            #pragma unroll
            for (int bq = 0; bq < 3 - a; ++bq)
                if (bp[bq] > bp[bq + 1]) { int t = bp[bq]; bp[bq] = bp[bq + 1]; bp[bq + 1] = t; }
        #pragma unroll
        for (int i = 0; i < 4; ++i) dC.piv[tid][i] = bp[i];

        // XOR table over the raw mask basis: bit i of t toggles m[i]
        int V[16]; V[0] = 0;
        #pragma unroll
        for (int t = 1; t < 16; ++t) V[t] = V[t & (t - 1)] ^ m[__ffs(t) - 1];
        #pragma unroll
        for (int t = 0; t < 16; ++t) dC.V[tid][t] = V[t];

        #pragma unroll
        for (int i = 0; i < 4; ++i) {
            int L = 0, f = fg[4 * tid + i];
            #pragma unroll
            for (int t = 0; t < 16; ++t) L |= (__popc(f & V[t]) & 1) << t;
            dC.lut[tid][i] = L;
        }
    }
}

// insert zero bits at 4 sorted pivot positions
__device__ __forceinline__ int expand4(int p, const int* bp)
{
    #pragma unroll
    for (int i = 0; i < 4; ++i) {
        int m = (1 << bp[i]) - 1;
        p = ((p & ~m) << 1) | (p & m);
    }
    return p;
}

__device__ __forceinline__ float sgnxor(float v, unsigned sb)
{
    return __int_as_float(__float_as_int(v) ^ sb);
}

// ---------------- main kernel ----------------
__global__ __launch_bounds__(NTHREADS, 1)
void qnn_kernel(const float* __restrict__ x, float* __restrict__ out)
{
    extern __shared__ float2 sAmp[];       // [QDIM], 128 KB

    __shared__ Consts sC;
    __shared__ float cq[NQ], sq[NQ];
    __shared__ float tabLo[128], tabHi[128];
    __shared__ float redbuf[NTHREADS / 32];

    const int tid = threadIdx.x;
    const int b   = blockIdx.x;

    // copy constants to smem
    {
        const int n = (int)(sizeof(Consts) / 4);
        const int* src = (const int*)&dC;
        int* dst = (int*)&sC;
        for (int i = tid; i < n; i += NTHREADS) dst[i] = src[i];
    }

    if (tid < NQ) {
        float ang = x[b * NQ + tid] * 1.57079632679489662f;
        float s, c;
        sincosf(ang, &s, &c);
        cq[tid] = c;
        sq[tid] = s;
    }
    __syncthreads();

    // product-state tables (initial RY layer on |0...0>)
    if (tid < 128) {
        float p = 1.0f;
        #pragma unroll
        for (int k = 0; k < 7; ++k)
            p *= ((tid >> k) & 1) ? sq[NQ - 1 - k] : cq[NQ - 1 - k];
        tabLo[tid] = p;
    } else if (tid < 256) {
        int m = tid - 128;
        float p = 1.0f;
        #pragma unroll
        for (int k = 0; k < 7; ++k)
            p *= ((m >> k) & 1) ? sq[6 - k] : cq[6 - k];
        tabHi[m] = p;
    }
    __syncthreads();

    #pragma unroll
    for (int k = 0; k < QDIM / NTHREADS; ++k) {
        int j = tid + k * NTHREADS;
        sAmp[j] = make_float2(tabHi[j >> 7] * tabLo[j & 127], 0.0f);
    }

    // ---- 28 fused passes of 4 gates each ----
    for (int p = 0; p < NPASS; ++p) {
        __syncthreads();

        int Vt[16];
        #pragma unroll
        for (int t = 0; t < 16; ++t) Vt[t] = sC.V[p][t];

        const int jb0 = expand4(tid,            sC.piv[p]);
        const int jb1 = expand4(tid + NTHREADS, sC.piv[p]);

        float2 a0[16], a1[16];
        #pragma unroll
        for (int t = 0; t < 16; ++t) a0[t] = sAmp[jb0 ^ Vt[t]];
        #pragma unroll
        for (int t = 0; t < 16; ++t) a1[t] = sAmp[jb1 ^ Vt[t]];

        #pragma unroll
        for (int i = 0; i < 4; ++i) {
            const float cz = sC.trig[p][i][0];
            const float sz = sC.trig[p][i][1];
            const float cy = sC.trig[p][i][2];
            const float sy = sC.trig[p][i][3];
            const int   f  = sC.F[p][i];
            const int   L  = sC.lut[p][i];
            const int   bit = 1 << i;

            const unsigned sl0 = (unsigned)(L ^ ((__popc(f & jb0) & 1) ? 0xFFFF : 0));
            const unsigned sl1 = (unsigned)(L ^ ((__popc(f & jb1) & 1) ? 0xFFFF : 0));

            #pragma unroll
            for (int t = 0; t < 16; ++t) {
                if (t & bit) continue;            // enumerate pairs (t, t|bit)
                const int t1 = t | bit;
                {   // group 0
                    unsigned sb = ((~(sl0 >> t)) & 1u) << 31;   // sigma=-1 when parity bit 0
                    float P = sgnxor(sz, sb), Q = sgnxor(sy, sb);
                    float ar = a0[t].x,  ai = a0[t].y;
                    float br = a0[t1].x, bi = a0[t1].y;
                    float zr =  ar * cz - ai * P;
                    float zi =  ar * P  + ai * cz;
                    float wr =  br * cz + bi * P;
                    float wi = -br * P  + bi * cz;
                    a0[t]  = make_float2(cy * zr + Q * wr, cy * zi + Q * wi);
                    a0[t1] = make_float2(cy * wr - Q * zr, cy * wi - Q * zi);
                }
                {   // group 1
                    unsigned sb = ((~(sl1 >> t)) & 1u) << 31;
                    float P = sgnxor(sz, sb), Q = sgnxor(sy, sb);
                    float ar = a1[t].x,  ai = a1[t].y;
                    float br = a1[t1].x, bi = a1[t1].y;
                    float zr =  ar * cz - ai * P;
                    float zi =  ar * P  + ai * cz;
                    float wr =  br * cz + bi * P;
                    float wi = -br * P  + bi * cz;
                    a1[t]  = make_float2(cy * zr + Q * wr, cy * zi + Q * wi);
                    a1[t1] = make_float2(cy * wr - Q * zr, cy * wi - Q * zi);
                }
            }
        }

        #pragma unroll
        for (int t = 0; t < 16; ++t) sAmp[jb0 ^ Vt[t]] = a0[t];
        #pragma unroll
        for (int t = 0; t < 16; ++t) sAmp[jb1 ^ Vt[t]] = a1[t];
    }
    __syncthreads();

    // ---- expectation value ----
    const int ff = sC.ffin;
    float acc = 0.0f;
    #pragma unroll
    for (int k = 0; k < QDIM / NTHREADS; ++k) {
        int j = tid + k * NTHREADS;
        float2 a = sAmp[j];
        float pr = a.x * a.x + a.y * a.y;
        acc += (__popc(ff & j) & 1) ? -pr : pr;
    }
    #pragma unroll
    for (int off = 16; off > 0; off >>= 1)
        acc += __shfl_down_sync(0xffffffffu, acc, off);
    if ((tid & 31) == 0) redbuf[tid >> 5] = acc;
    __syncthreads();
    if (tid < 32) {
        float t = (tid < NTHREADS / 32) ? redbuf[tid] : 0.0f;
        #pragma unroll
        for (int off = 8; off > 0; off >>= 1)
            t += __shfl_down_sync(0xffffffffu, t, off);
        if (tid == 0) out[b] = (t + 1.0f) * 0.5f;
    }
}

extern "C" void kernel_launch(void* const* d_in, const int* in_sizes, int n_in,
                              void* d_out, int out_size)
{
    const float* x      = (const float*)d_in[0];   // (2048, 14)
    const float* params = (const float*)d_in[1];   // (224,)
    float* out          = (float*)d_out;           // (2048,)
    (void)in_sizes; (void)n_in;

    qnn_setup<<<1, 128>>>(params);

    const size_t shmem = (size_t)QDIM * sizeof(float2);   // 128 KB
    cudaFuncSetAttribute(qnn_kernel,
                         cudaFuncAttributeMaxDynamicSharedMemorySize,
                         (int)shmem);
    qnn_kernel<<<out_size, NTHREADS, shmem>>>(x, out);
}